// round 1
// baseline (speedup 1.0000x reference)
#include <cuda_runtime.h>

// SingleCurveDeformLayer: two Euler steps of a Gaussian-RBF point flow.
//   land = concat(src, tgt)            [B, 4096, 2]
//   dp1_i = sum_{j<2048} exp(-|x_i - s_j|^2 / s2) * p_j     (all 4096 rows)
//   shape1 = land + 0.5*dp1
//   dp2_i = sum_{j<2048} exp(-|s1_i - s1_j|^2 / s2) * p_j   (target rows only)
//   out = (shape1 + 0.5*dp2)[targets]
//
// Math: with c = -log2(e)/s2,  w = 2^(c*r_i + a_j + u_j*x_i + v_j*y_i)
//   a_j = c*|s_j|^2, u_j = -2c*s_jx, v_j = -2c*s_jy   (precomputed per source pt)
//
// Layout: lane = output row (32 rows/CTA), warp = j-chunk (8 warps x 256 j),
// source pack staged in smem so every warp load is an LDS broadcast (N=1).

#define NSRC  2048
#define NTGT  2048
#define NLAND 4096
#define NB    4
#define TAUF  0.5f
#define LOG2E 1.4426950408889634f

// Cross-kernel scratch (device globals; no allocation).
__device__ float4 g_pack2[NB * NSRC];   // (u2, v2, a2, px) from shape1 source pts
__device__ float2 g_s1t[NB * NTGT];     // shape1 of target rows

__device__ __forceinline__ float ex2f(float x) {
    float y;
    asm("ex2.approx.ftz.f32 %0, %1;" : "=f"(y) : "f"(x));
    return y;
}

// ---------------------------------------------------------------------------
// Pass 1: dp1 over all 4096 landmarks per batch.
//   grid = NB*NLAND/32 = 512 CTAs, 256 threads (8 warps).
// ---------------------------------------------------------------------------
__global__ __launch_bounds__(256) void pass1_kernel(
    const float2* __restrict__ mom,   // [B*NSRC]
    const float2* __restrict__ src,   // [B*NSRC]
    const float2* __restrict__ tgt,   // [B*NTGT]
    const float*  __restrict__ sig)   // [1] sigmaV2
{
    __shared__ float4 sA[NSRC];       // (u, v, a, px)
    __shared__ float  sPy[NSRC];
    __shared__ float2 red[8][32];

    const int base = blockIdx.x * 32;
    const int b    = base >> 12;            // / 4096
    const int i0   = base & (NLAND - 1);
    const int tid  = threadIdx.x;
    const int w    = tid >> 5;
    const int lane = tid & 31;

    const float c2   = -LOG2E / sig[0];
    const float m2c2 = -2.0f * c2;

    // Stage source pack into smem.
    for (int j = tid; j < NSRC; j += 256) {
        float2 s = src[b * NSRC + j];
        float2 p = mom[b * NSRC + j];
        sA[j]  = make_float4(m2c2 * s.x, m2c2 * s.y,
                             c2 * (s.x * s.x + s.y * s.y), p.x);
        sPy[j] = p.y;
    }
    __syncthreads();

    const int i = i0 + lane;
    float2 X = (i < NSRC) ? src[b * NSRC + i] : tgt[b * NTGT + (i - NSRC)];
    const float cri = c2 * (X.x * X.x + X.y * X.y);

    float ax0 = 0.f, ay0 = 0.f, ax1 = 0.f, ay1 = 0.f;
    const int jb = w * 256;
    #pragma unroll 4
    for (int t = 0; t < 256; t += 2) {
        float4 A  = sA[jb + t];
        float  py = sPy[jb + t];
        float arg = fmaf(A.y, X.y, fmaf(A.x, X.x, A.z)) + cri;
        float wt  = ex2f(arg);
        ax0 = fmaf(wt, A.w, ax0);
        ay0 = fmaf(wt, py,  ay0);

        float4 A1  = sA[jb + t + 1];
        float  py1 = sPy[jb + t + 1];
        float arg1 = fmaf(A1.y, X.y, fmaf(A1.x, X.x, A1.z)) + cri;
        float wt1  = ex2f(arg1);
        ax1 = fmaf(wt1, A1.w, ax1);
        ay1 = fmaf(wt1, py1,  ay1);
    }
    red[w][lane] = make_float2(ax0 + ax1, ay0 + ay1);
    __syncthreads();

    if (tid < 32) {   // warp 0, lane == row index; X is this row's position
        float sx = 0.f, sy = 0.f;
        #pragma unroll
        for (int ww = 0; ww < 8; ww++) {
            float2 r = red[ww][lane];
            sx += r.x;
            sy += r.y;
        }
        float s1x = fmaf(TAUF, sx, X.x);
        float s1y = fmaf(TAUF, sy, X.y);
        if (i < NSRC) {
            // Source row: emit pass-2 pack built from shape1 position.
            float2 p = mom[b * NSRC + i];
            g_pack2[b * NSRC + i] =
                make_float4(m2c2 * s1x, m2c2 * s1y,
                            c2 * (s1x * s1x + s1y * s1y), p.x);
        } else {
            g_s1t[b * NTGT + (i - NSRC)] = make_float2(s1x, s1y);
        }
    }
}

// ---------------------------------------------------------------------------
// Pass 2: dp2 over the 2048 target rows per batch; writes output.
//   grid = NB*NTGT/32 = 256 CTAs, 256 threads.
// ---------------------------------------------------------------------------
__global__ __launch_bounds__(256) void pass2_kernel(
    const float2* __restrict__ mom,
    const float*  __restrict__ sig,
    float2*       __restrict__ out)   // [B*NTGT]
{
    __shared__ float4 sA[NSRC];
    __shared__ float  sPy[NSRC];
    __shared__ float2 red[8][32];

    const int base = blockIdx.x * 32;
    const int b    = base >> 11;            // / 2048
    const int i0   = base & (NTGT - 1);
    const int tid  = threadIdx.x;
    const int w    = tid >> 5;
    const int lane = tid & 31;

    const float c2 = -LOG2E / sig[0];

    for (int j = tid; j < NSRC; j += 256) {
        sA[j]  = g_pack2[b * NSRC + j];
        sPy[j] = mom[b * NSRC + j].y;
    }
    __syncthreads();

    const int i = i0 + lane;
    float2 X = g_s1t[b * NTGT + i];
    const float cri = c2 * (X.x * X.x + X.y * X.y);

    float ax0 = 0.f, ay0 = 0.f, ax1 = 0.f, ay1 = 0.f;
    const int jb = w * 256;
    #pragma unroll 4
    for (int t = 0; t < 256; t += 2) {
        float4 A  = sA[jb + t];
        float  py = sPy[jb + t];
        float arg = fmaf(A.y, X.y, fmaf(A.x, X.x, A.z)) + cri;
        float wt  = ex2f(arg);
        ax0 = fmaf(wt, A.w, ax0);
        ay0 = fmaf(wt, py,  ay0);

        float4 A1  = sA[jb + t + 1];
        float  py1 = sPy[jb + t + 1];
        float arg1 = fmaf(A1.y, X.y, fmaf(A1.x, X.x, A1.z)) + cri;
        float wt1  = ex2f(arg1);
        ax1 = fmaf(wt1, A1.w, ax1);
        ay1 = fmaf(wt1, py1,  ay1);
    }
    red[w][lane] = make_float2(ax0 + ax1, ay0 + ay1);
    __syncthreads();

    if (tid < 32) {
        float sx = 0.f, sy = 0.f;
        #pragma unroll
        for (int ww = 0; ww < 8; ww++) {
            float2 r = red[ww][lane];
            sx += r.x;
            sy += r.y;
        }
        out[b * NTGT + i] = make_float2(fmaf(TAUF, sx, X.x),
                                        fmaf(TAUF, sy, X.y));
    }
}

// ---------------------------------------------------------------------------
extern "C" void kernel_launch(void* const* d_in, const int* in_sizes, int n_in,
                              void* d_out, int out_size)
{
    const float2* mom = (const float2*)d_in[0];   // momentum    [B,2048,2]
    const float2* src = (const float2*)d_in[1];   // source_init [B,2048,2]
    const float2* tgt = (const float2*)d_in[2];   // target_init [B,2048,2]
    const float*  sig = (const float*)d_in[3];    // sigmaV2 scalar
    float2* out = (float2*)d_out;                 // [B,2048,2] float32

    pass1_kernel<<<NB * NLAND / 32, 256>>>(mom, src, tgt, sig);
    pass2_kernel<<<NB * NTGT / 32, 256>>>(mom, sig, out);
}